// round 2
// baseline (speedup 1.0000x reference)
#include <cuda_runtime.h>
#include <cuda_bf16.h>

// PyramidROIAlign: B=1, N rois, C=256, 7x7 bilinear crop from one of P2..P5.
// One 256-thread block per ROI. Threads 0..48 precompute per-position bilinear
// metadata into shared memory; then all threads stream 49*64 float4 tasks
// (coalesced over channels). Output written with .cs streaming stores.

#define POOL_H 7
#define POOL_W 7
#define NPOS   (POOL_H * POOL_W)
#define C      256
#define CQ     (C / 4)   // float4 groups per position

__global__ __launch_bounds__(256, 8) void pyramid_roi_align_kernel(
    const float* __restrict__ boxes,   // [N,4] y1,x1,y2,x2 normalized
    const float* __restrict__ meta,    // [93], meta[4],meta[5] = image H,W
    const float* __restrict__ P2,      // [256,256,256]
    const float* __restrict__ P3,      // [128,128,256]
    const float* __restrict__ P4,      // [64,64,256]
    const float* __restrict__ P5,      // [32,32,256]
    float* __restrict__ out)           // [N,7,7,256]
{
    const int n   = blockIdx.x;
    const int tid = threadIdx.x;

    __shared__ int   s_off00[NPOS], s_off01[NPOS], s_off10[NPOS], s_off11[NPOS];
    __shared__ float s_wx[NPOS], s_wy[NPOS];
    __shared__ const float* s_fmap;

    if (tid < NPOS) {
        const float y1 = boxes[n * 4 + 0];
        const float x1 = boxes[n * 4 + 1];
        const float y2 = boxes[n * 4 + 2];
        const float x2 = boxes[n * 4 + 3];
        const float h = y2 - y1;
        const float w = x2 - x1;

        // roi_level = clip(4 + round(log2(sqrt(h*w) / (224/sqrt(imgH*imgW)))), 2, 5)
        const float img_h = meta[4];
        const float img_w = meta[5];
        const float scale = 224.0f / sqrtf(img_h * img_w);   // 0.21875 for 1024x1024
        const float lvl_f = log2f(sqrtf(h * w) / scale);
        int level = 4 + (int)rintf(lvl_f);                    // rint = round-half-even, matches jnp.round
        level = min(max(level, 2), 5);

        const int H = 1024 >> level;   // 256,128,64,32 for levels 2..5
        const int W = H;

        const int py = tid / POOL_W;
        const int px = tid % POOL_W;
        const float ty = (float)py / (float)(POOL_H - 1);
        const float tx = (float)px / (float)(POOL_W - 1);

        const float ys = (y1 + ty * h) * (float)(H - 1);
        const float xs = (x1 + tx * w) * (float)(W - 1);

        const float y0f = fminf(fmaxf(floorf(ys), 0.0f), (float)(H - 1));
        const float x0f = fminf(fmaxf(floorf(xs), 0.0f), (float)(W - 1));
        const int y0  = (int)y0f;
        const int x0  = (int)x0f;
        const int y1i = min(y0 + 1, H - 1);
        const int x1i = min(x0 + 1, W - 1);

        s_wy[tid] = ys - y0f;
        s_wx[tid] = xs - x0f;
        s_off00[tid] = (y0  * W + x0 ) * C;
        s_off01[tid] = (y0  * W + x1i) * C;
        s_off10[tid] = (y1i * W + x0 ) * C;
        s_off11[tid] = (y1i * W + x1i) * C;

        if (tid == 0) {
            s_fmap = (level == 2) ? P2 : (level == 3) ? P3 : (level == 4) ? P4 : P5;
        }
    }
    __syncthreads();

    const float* __restrict__ fmap = s_fmap;
    float* __restrict__ out_base = out + (long long)n * (NPOS * C);

    // 49 positions * 64 float4 channel groups = 3136 tasks; 256 threads -> ~12.25 iters.
    #pragma unroll 1
    for (int i = tid; i < NPOS * CQ; i += 256) {
        const int pos = i >> 6;          // / CQ
        const int cg  = (i & 63) << 2;   // channel offset (floats)

        const float wx = s_wx[pos];
        const float wy = s_wy[pos];

        const float4 v00 = __ldg((const float4*)(fmap + s_off00[pos] + cg));
        const float4 v01 = __ldg((const float4*)(fmap + s_off01[pos] + cg));
        const float4 v10 = __ldg((const float4*)(fmap + s_off10[pos] + cg));
        const float4 v11 = __ldg((const float4*)(fmap + s_off11[pos] + cg));

        float4 r;
        {
            const float top_x = v00.x + (v01.x - v00.x) * wx;
            const float bot_x = v10.x + (v11.x - v10.x) * wx;
            r.x = top_x + (bot_x - top_x) * wy;
            const float top_y = v00.y + (v01.y - v00.y) * wx;
            const float bot_y = v10.y + (v11.y - v10.y) * wx;
            r.y = top_y + (bot_y - top_y) * wy;
            const float top_z = v00.z + (v01.z - v00.z) * wx;
            const float bot_z = v10.z + (v11.z - v10.z) * wx;
            r.z = top_z + (bot_z - top_z) * wy;
            const float top_w = v00.w + (v01.w - v00.w) * wx;
            const float bot_w = v10.w + (v11.w - v10.w) * wx;
            r.w = top_w + (bot_w - top_w) * wy;
        }

        __stcs((float4*)(out_base + pos * C + cg), r);
    }
}

extern "C" void kernel_launch(void* const* d_in, const int* in_sizes, int n_in,
                              void* d_out, int out_size) {
    const float* boxes = (const float*)d_in[0];   // ROIboxes [1,N,4]
    const float* meta  = (const float*)d_in[1];   // image_meta [1,93]
    const float* P2    = (const float*)d_in[2];
    const float* P3    = (const float*)d_in[3];
    const float* P4    = (const float*)d_in[4];
    const float* P5    = (const float*)d_in[5];
    float* out = (float*)d_out;

    const int N = in_sizes[0] / 4;
    pyramid_roi_align_kernel<<<N, 256>>>(boxes, meta, P2, P3, P4, P5, out);
}

// round 5
// speedup vs baseline: 1.0706x; 1.0706x over previous
#include <cuda_runtime.h>
#include <cuda_bf16.h>

// PyramidROIAlign: B=1, N rois, C=256, 7x7 bilinear crop from one of P2..P5.
// One 256-thread block per ROI. Threads 0..48 precompute per-position bilinear
// metadata into shared memory; main loop is manually 2-way unrolled so 8
// LDG.128 are in flight per warp before any FMA consumes them.

#define POOL_H 7
#define POOL_W 7
#define NPOS   (POOL_H * POOL_W)
#define C      256
#define CQ     (C / 4)            // float4 groups per position
#define NTASK  (NPOS * CQ)        // 3136

__device__ __forceinline__ float4 lerp2d(float4 v00, float4 v01, float4 v10, float4 v11,
                                         float wx, float wy) {
    float4 r;
    float tx, bx;
    tx = v00.x + (v01.x - v00.x) * wx;  bx = v10.x + (v11.x - v10.x) * wx;  r.x = tx + (bx - tx) * wy;
    tx = v00.y + (v01.y - v00.y) * wx;  bx = v10.y + (v11.y - v10.y) * wx;  r.y = tx + (bx - tx) * wy;
    tx = v00.z + (v01.z - v00.z) * wx;  bx = v10.z + (v11.z - v10.z) * wx;  r.z = tx + (bx - tx) * wy;
    tx = v00.w + (v01.w - v00.w) * wx;  bx = v10.w + (v11.w - v10.w) * wx;  r.w = tx + (bx - tx) * wy;
    return r;
}

__global__ __launch_bounds__(256) void pyramid_roi_align_kernel(
    const float* __restrict__ boxes,   // [N,4] y1,x1,y2,x2 normalized
    const float* __restrict__ meta,    // [93], meta[4],meta[5] = image H,W
    const float* __restrict__ P2,      // [256,256,256]
    const float* __restrict__ P3,      // [128,128,256]
    const float* __restrict__ P4,      // [64,64,256]
    const float* __restrict__ P5,      // [32,32,256]
    float* __restrict__ out)           // [N,7,7,256]
{
    const int n   = blockIdx.x;
    const int tid = threadIdx.x;

    __shared__ int   s_off00[NPOS], s_off01[NPOS], s_off10[NPOS], s_off11[NPOS];
    __shared__ float s_wx[NPOS], s_wy[NPOS];
    __shared__ const float* s_fmap;

    if (tid < NPOS) {
        const float y1 = boxes[n * 4 + 0];
        const float x1 = boxes[n * 4 + 1];
        const float y2 = boxes[n * 4 + 2];
        const float x2 = boxes[n * 4 + 3];
        const float h = y2 - y1;
        const float w = x2 - x1;

        // roi_level = clip(4 + round(log2(sqrt(h*w) / (224/sqrt(imgH*imgW)))), 2, 5)
        const float img_h = meta[4];
        const float img_w = meta[5];
        const float scale = 224.0f / sqrtf(img_h * img_w);
        const float lvl_f = log2f(sqrtf(h * w) / scale);
        int level = 4 + (int)rintf(lvl_f);         // round-half-even, matches jnp.round
        level = min(max(level, 2), 5);

        const int H = 1024 >> level;               // 256,128,64,32
        const int W = H;

        const int py = tid / POOL_W;
        const int px = tid % POOL_W;
        const float ty = (float)py * (1.0f / (POOL_H - 1));
        const float tx = (float)px * (1.0f / (POOL_W - 1));

        const float ys = (y1 + ty * h) * (float)(H - 1);
        const float xs = (x1 + tx * w) * (float)(W - 1);

        const float y0f = fminf(fmaxf(floorf(ys), 0.0f), (float)(H - 1));
        const float x0f = fminf(fmaxf(floorf(xs), 0.0f), (float)(W - 1));
        const int y0  = (int)y0f;
        const int x0  = (int)x0f;
        const int y1i = min(y0 + 1, H - 1);
        const int x1i = min(x0 + 1, W - 1);

        s_wy[tid] = ys - y0f;
        s_wx[tid] = xs - x0f;
        s_off00[tid] = (y0  * W + x0 ) * C;
        s_off01[tid] = (y0  * W + x1i) * C;
        s_off10[tid] = (y1i * W + x0 ) * C;
        s_off11[tid] = (y1i * W + x1i) * C;

        if (tid == 0) {
            s_fmap = (level == 2) ? P2 : (level == 3) ? P3 : (level == 4) ? P4 : P5;
        }
    }
    __syncthreads();

    const float* __restrict__ fmap = s_fmap;
    float* __restrict__ out_base = out + (long long)n * (NPOS * C);

    // 3136 tasks, 2 per loop iteration per thread (stride 512).
    #pragma unroll 1
    for (int i = tid; i < NTASK; i += 512) {
        const int j      = i + 256;
        const bool has_b = (j < NTASK);

        // ---- gather metadata for both tasks first (LDS off the critical path)
        const int posA = i >> 6;
        const int cgA  = (i & 63) << 2;
        const float wxA = s_wx[posA], wyA = s_wy[posA];
        const int oA00 = s_off00[posA] + cgA;
        const int oA01 = s_off01[posA] + cgA;
        const int oA10 = s_off10[posA] + cgA;
        const int oA11 = s_off11[posA] + cgA;

        const int posB = has_b ? (j >> 6) : posA;
        const int cgB  = has_b ? ((j & 63) << 2) : cgA;
        const float wxB = s_wx[posB], wyB = s_wy[posB];
        const int oB00 = s_off00[posB] + cgB;
        const int oB01 = s_off01[posB] + cgB;
        const int oB10 = s_off10[posB] + cgB;
        const int oB11 = s_off11[posB] + cgB;

        // ---- issue all 8 loads back-to-back (MLP=8)
        const float4 a00 = __ldg((const float4*)(fmap + oA00));
        const float4 a01 = __ldg((const float4*)(fmap + oA01));
        const float4 a10 = __ldg((const float4*)(fmap + oA10));
        const float4 a11 = __ldg((const float4*)(fmap + oA11));
        const float4 b00 = __ldg((const float4*)(fmap + oB00));
        const float4 b01 = __ldg((const float4*)(fmap + oB01));
        const float4 b10 = __ldg((const float4*)(fmap + oB10));
        const float4 b11 = __ldg((const float4*)(fmap + oB11));

        // ---- compute + store
        const float4 rA = lerp2d(a00, a01, a10, a11, wxA, wyA);
        __stcs((float4*)(out_base + posA * C + cgA), rA);

        if (has_b) {
            const float4 rB = lerp2d(b00, b01, b10, b11, wxB, wyB);
            __stcs((float4*)(out_base + posB * C + cgB), rB);
        }
    }
}

extern "C" void kernel_launch(void* const* d_in, const int* in_sizes, int n_in,
                              void* d_out, int out_size) {
    const float* boxes = (const float*)d_in[0];   // ROIboxes [1,N,4]
    const float* meta  = (const float*)d_in[1];   // image_meta [1,93]
    const float* P2    = (const float*)d_in[2];
    const float* P3    = (const float*)d_in[3];
    const float* P4    = (const float*)d_in[4];
    const float* P5    = (const float*)d_in[5];
    float* out = (float*)d_out;

    const int N = in_sizes[0] / 4;
    pyramid_roi_align_kernel<<<N, 256>>>(boxes, meta, P2, P3, P4, P5, out);
}